// round 15
// baseline (speedup 1.0000x reference)
#include <cuda_runtime.h>
#include <cuda_fp16.h>
#include <math.h>

#define B_ 2
#define S_ 2048
#define D_ 2048
#define H_ 32
#define G_ 8
#define HD_ 64
#define GS_ (H_/G_)
#define M_ (B_*S_)

typedef unsigned int uint32;

// ---- tensor-core helpers (fp16 path) ----
__device__ __forceinline__ void ldsm4(uint32 &r0, uint32 &r1, uint32 &r2, uint32 &r3,
                                      const void* p) {
    uint32 a = (uint32)__cvta_generic_to_shared(p);
    asm volatile("ldmatrix.sync.aligned.m8n8.x4.shared.b16 {%0,%1,%2,%3},[%4];"
                 : "=r"(r0), "=r"(r1), "=r"(r2), "=r"(r3) : "r"(a));
}
__device__ __forceinline__ void ldsm2t(uint32 &r0, uint32 &r1, const void* p) {
    uint32 a = (uint32)__cvta_generic_to_shared(p);
    asm volatile("ldmatrix.sync.aligned.m8n8.x2.trans.shared.b16 {%0,%1},[%2];"
                 : "=r"(r0), "=r"(r1) : "r"(a));
}
// fp32-accumulate MMA
__device__ __forceinline__ void mma16816h(float c[4], const uint32 a[4],
                                          uint32 b0, uint32 b1) {
    asm volatile(
        "mma.sync.aligned.m16n8k16.row.col.f32.f16.f16.f32 "
        "{%0,%1,%2,%3},{%4,%5,%6,%7},{%8,%9},{%0,%1,%2,%3};"
        : "+f"(c[0]), "+f"(c[1]), "+f"(c[2]), "+f"(c[3])
        : "r"(a[0]), "r"(a[1]), "r"(a[2]), "r"(a[3]), "r"(b0), "r"(b1));
}
// fp16-accumulate MMA (for small correction terms)
__device__ __forceinline__ void mma16816hh(uint32 c[2], const uint32 a[4],
                                           uint32 b0, uint32 b1) {
    asm volatile(
        "mma.sync.aligned.m16n8k16.row.col.f16.f16.f16.f16 "
        "{%0,%1},{%2,%3,%4,%5},{%6,%7},{%0,%1};"
        : "+r"(c[0]), "+r"(c[1])
        : "r"(a[0]), "r"(a[1]), "r"(a[2]), "r"(a[3]), "r"(b0), "r"(b1));
}
__device__ __forceinline__ void addh2(float &x, float &y, uint32 p) {
    __half2 hv = *(__half2*)&p;
    float2 f = __half22float2(hv);
    x += f.x; y += f.y;
}
__device__ __forceinline__ void split2h(float p0, float p1, uint32 &h, uint32 &l) {
    __half2 hh = __floats2half2_rn(p0, p1);
    float2 hf = __half22float2(hh);
    __half2 ll = __floats2half2_rn(p0 - hf.x, p1 - hf.y);
    h = *(uint32*)&hh;
    l = *(uint32*)&ll;
}
__device__ __forceinline__ uint32 pack2h(float p0, float p1) {
    __half2 hh = __floats2half2_rn(p0, p1);
    return *(uint32*)&hh;
}
__device__ __forceinline__ void cvt4h(float4 v, uint2 &hi, uint2 &lo) {
    split2h(v.x, v.y, hi.x, lo.x);
    split2h(v.z, v.w, hi.y, lo.y);
}
__device__ __forceinline__ uint2 cvt4h1(float4 v) {
    return make_uint2(pack2h(v.x, v.y), pack2h(v.z, v.w));
}

// ---- Scratch ----
__device__ float g_q[(size_t)M_*H_*HD_];
__device__ float g_k[(size_t)M_*G_*HD_];
__device__ float g_ctx[(size_t)M_*H_*HD_];
__device__ __half g_wqh[(size_t)H_*HD_*D_];
__device__ __half g_wkh[(size_t)G_*HD_*D_];
__device__ __half g_wvh[(size_t)G_*HD_*D_];
__device__ __half g_woh[(size_t)D_*H_*HD_];
__device__ __half g_qh[(size_t)M_*H_*HD_], g_ql[(size_t)M_*H_*HD_];
__device__ __half g_kh[(size_t)M_*G_*HD_];
__device__ __half g_vh[(size_t)M_*G_*HD_];

// ---------------------------------------------------------------------------
// Weight fp32 -> fp16 conversion (one pass over Wq|Wk|Wv|Wo)
// ---------------------------------------------------------------------------
#define WQ4 1048576u
#define WK4 262144u
#define WV4 262144u
#define WO4 1048576u
#define WTOT4 (WQ4+WK4+WV4+WO4)

__global__ __launch_bounds__(256) void wconv(
    const float* __restrict__ Wq, const float* __restrict__ Wk,
    const float* __restrict__ Wv, const float* __restrict__ Wo)
{
    uint32 i = blockIdx.x * 256 + threadIdx.x;
    if (i >= WTOT4) return;
    const float* src; __half* dst; uint32 off;
    if (i < WQ4)                   { src = Wq; dst = g_wqh; off = i; }
    else if (i < WQ4 + WK4)        { src = Wk; dst = g_wkh; off = i - WQ4; }
    else if (i < WQ4 + WK4 + WV4)  { src = Wv; dst = g_wvh; off = i - WQ4 - WK4; }
    else                           { src = Wo; dst = g_woh; off = i - WQ4 - WK4 - WV4; }
    float4 v = ((const float4*)src)[off];
    ((uint2*)dst)[off] = cvt4h1(v);
}

// ---------------------------------------------------------------------------
// NT GEMM: A fp32 (split hi/lo in-kernel), B fp16 pre-converted. (R14 frozen)
// ---------------------------------------------------------------------------
#define BM 128
#define BN 64
#define BKK 32
#define ASTR 40
#define STAGE_ELEMS (BM*ASTR*2 + BN*ASTR)
#define SMEM_BYTES  (2 * STAGE_ELEMS * 2)

__device__ __forceinline__ void gemm_body(
    const float* __restrict__ A, const __half* __restrict__ Bg,
    float* __restrict__ Cf, __half* __restrict__ Ch,
    int N, int K, int m0, int n0, __half* sm)
{
    const int tid  = threadIdx.x;
    const int lane = tid & 31;
    const int warp = tid >> 5;
    const int wm = (warp >> 1) * 32;
    const int wn = (warp & 1) * 32;

    const int a_lr = lane & 15;
    const int a_k8 = ((lane >> 4) & 1) << 3;
    const int b_nr = (((lane >> 4) & 1) << 3) | (lane & 7);
    const int b_k8 = ((lane >> 3) & 1) << 3;

    float acc[2][4][4];
    #pragma unroll
    for (int i = 0; i < 2; i++)
        #pragma unroll
        for (int j = 0; j < 4; j++)
            #pragma unroll
            for (int t = 0; t < 4; t++) acc[i][j][t] = 0.f;

    const int b_row = tid >> 2, b_c8 = (tid & 3) << 3;
    float4 ar[4]; uint4 br;
    #pragma unroll
    for (int it = 0; it < 4; it++) {
        int f = it * 256 + tid, row = f >> 3, c4 = f & 7;
        ar[it] = *(const float4*)(A + (size_t)(m0 + row) * K + c4 * 4);
    }
    br = *(const uint4*)(Bg + (size_t)(n0 + b_row) * K + b_c8);

    for (int kb = 0; kb < K; kb += BKK) {
        const int st = (kb >> 5) & 1;
        __half* Ah = sm + st * STAGE_ELEMS;
        __half* Al = Ah + BM * ASTR;
        __half* Bh = Al + BM * ASTR;

        #pragma unroll
        for (int it = 0; it < 4; it++) {
            int f = it * 256 + tid, row = f >> 3, c4 = f & 7;
            uint2 hi, lo; cvt4h(ar[it], hi, lo);
            *(uint2*)&Ah[row * ASTR + c4 * 4] = hi;
            *(uint2*)&Al[row * ASTR + c4 * 4] = lo;
        }
        *(uint4*)&Bh[b_row * ASTR + b_c8] = br;
        __syncthreads();

        if (kb + BKK < K) {
            #pragma unroll
            for (int it = 0; it < 4; it++) {
                int f = it * 256 + tid, row = f >> 3, c4 = f & 7;
                ar[it] = *(const float4*)(A + (size_t)(m0 + row) * K + kb + BKK + c4 * 4);
            }
            br = *(const uint4*)(Bg + (size_t)(n0 + b_row) * K + kb + BKK + b_c8);
        }

        #pragma unroll
        for (int ks = 0; ks < BKK; ks += 16) {
            uint32 ah[2][4], al[2][4], bh[2][4];
            #pragma unroll
            for (int mi = 0; mi < 2; mi++) {
                int off = (wm + mi * 16 + a_lr) * ASTR + ks + a_k8;
                ldsm4(ah[mi][0], ah[mi][1], ah[mi][2], ah[mi][3], &Ah[off]);
                ldsm4(al[mi][0], al[mi][1], al[mi][2], al[mi][3], &Al[off]);
            }
            #pragma unroll
            for (int p = 0; p < 2; p++) {
                int off = (wn + p * 16 + b_nr) * ASTR + ks + b_k8;
                ldsm4(bh[p][0], bh[p][1], bh[p][2], bh[p][3], &Bh[off]);
            }
            #pragma unroll
            for (int mi = 0; mi < 2; mi++)
                #pragma unroll
                for (int ni = 0; ni < 4; ni++) {
                    int p = ni >> 1, s = (ni & 1) * 2;
                    mma16816h(acc[mi][ni], ah[mi], bh[p][s], bh[p][s+1]);
                    mma16816h(acc[mi][ni], al[mi], bh[p][s], bh[p][s+1]);
                }
        }
    }

    const int gq = lane >> 2, t = lane & 3;
    if (Ch) {
        #pragma unroll
        for (int mi = 0; mi < 2; mi++)
            #pragma unroll
            for (int ni = 0; ni < 4; ni++) {
                int row = m0 + wm + mi * 16 + gq;
                int col = n0 + wn + ni * 8 + t * 2;
                *(uint32*)(Ch + (size_t)row * N + col) =
                    pack2h(acc[mi][ni][0], acc[mi][ni][1]);
                *(uint32*)(Ch + (size_t)(row + 8) * N + col) =
                    pack2h(acc[mi][ni][2], acc[mi][ni][3]);
            }
    } else {
        #pragma unroll
        for (int mi = 0; mi < 2; mi++)
            #pragma unroll
            for (int ni = 0; ni < 4; ni++) {
                int row = m0 + wm + mi * 16 + gq;
                int col = n0 + wn + ni * 8 + t * 2;
                *(float2*)(Cf + (size_t)row * N + col)       = make_float2(acc[mi][ni][0], acc[mi][ni][1]);
                *(float2*)(Cf + (size_t)(row + 8) * N + col) = make_float2(acc[mi][ni][2], acc[mi][ni][3]);
            }
    }
}

__global__ __launch_bounds__(256, 2) void gemm_qkv(const float* __restrict__ x)
{
    extern __shared__ __half sm[];
    int nb = blockIdx.x;
    if (nb < 32)
        gemm_body(x, g_wqh, g_q, nullptr, H_*HD_, D_, blockIdx.y * BM, nb * 64, sm);
    else if (nb < 40)
        gemm_body(x, g_wkh, g_k, nullptr, G_*HD_, D_, blockIdx.y * BM, (nb - 32) * 64, sm);
    else
        gemm_body(x, g_wvh, nullptr, g_vh, G_*HD_, D_, blockIdx.y * BM, (nb - 40) * 64, sm);
}

__global__ __launch_bounds__(256, 2) void gemm_o(float* __restrict__ out)
{
    extern __shared__ __half sm[];
    gemm_body(g_ctx, g_woh, out, nullptr, D_, H_*HD_, blockIdx.y * BM, blockIdx.x * 64, sm);
}

// ---------------------------------------------------------------------------
// Fused RMSNorm + RoPE + scale, emitting fp16 (hi, optional lo). (R14 frozen)
// ---------------------------------------------------------------------------
__global__ __launch_bounds__(256) void rms_rope_h(
    const float* __restrict__ t, __half* __restrict__ th, __half* __restrict__ tl,
    const float* __restrict__ cosp, const float* __restrict__ sinp,
    const float* __restrict__ scale, int NH, float mul, int wlo)
{
    const int warp = (blockIdx.x * blockDim.x + threadIdx.x) >> 5;
    const int lane = threadIdx.x & 31;
    const int s = (warp / NH) % S_;
    const float* p = t + (size_t)warp * HD_;

    float t1 = p[lane];
    float t2 = p[lane + 32];
    float ss = t1 * t1 + t2 * t2;
    #pragma unroll
    for (int o = 16; o > 0; o >>= 1) ss += __shfl_xor_sync(0xffffffffu, ss, o);
    float rs = rsqrtf(ss * (1.0f / HD_) + 1e-6f);

    float n1 = t1 * rs * (1.0f + scale[lane]);
    float n2 = t2 * rs * (1.0f + scale[lane + 32]);

    float c1 = cosp[s * HD_ + lane],      c2 = cosp[s * HD_ + lane + 32];
    float s1 = sinp[s * HD_ + lane],      s2 = sinp[s * HD_ + lane + 32];
    float o1 = (n1 * c1 - n2 * s1) * mul;
    float o2 = (n2 * c2 + n1 * s2) * mul;

    size_t base = (size_t)warp * HD_;
    __half h1 = __float2half_rn(o1);
    __half h2 = __float2half_rn(o2);
    th[base + lane]      = h1;
    th[base + lane + 32] = h2;
    if (wlo) {
        tl[base + lane]      = __float2half_rn(o1 - __half2float(h1));
        tl[base + lane + 32] = __float2half_rn(o2 - __half2float(h2));
    }
}

// ---------------------------------------------------------------------------
// Tensor-core causal flash attention. fp16 inputs, double-buffered K/V,
// ONE sync/tile, longest-first. Lo-correction MMAs use fp16 ACCUMULATION
// (merged immediately to keep register lifetime short).
// ---------------------------------------------------------------------------
#define TSTR 72
#define NEG_BIG (-1e30f)

__global__ __launch_bounds__(128) void attn_tc(
    const __half* __restrict__ qh_g, const __half* __restrict__ ql_g,
    const __half* __restrict__ kh_g, const __half* __restrict__ vh_g,
    float* __restrict__ ctx)
{
    __shared__ __align__(16) __half Kh[2][64*TSTR];
    __shared__ __align__(16) __half Vh[2][64*TSTR];

    const int tid  = threadIdx.x;
    const int lane = tid & 31;
    const int warp = tid >> 5;
    const int qt = (S_/64 - 1) - blockIdx.x;   // longest-first
    const int h  = blockIdx.y, b = blockIdx.z;
    const int g  = h / GS_;
    const int q0 = qt * 64;

    const int a_lr = lane & 15;
    const int a_k8 = ((lane >> 4) & 1) << 3;
    const int b_nr = (((lane >> 4) & 1) << 3) | (lane & 7);
    const int b_k8 = ((lane >> 3) & 1) << 3;
    const int v_r  = lane & 15;

    // ---- Q tile: hi into Kh[1], lo into Vh[1] (512 chunks of 8 halves) ----
    #pragma unroll
    for (int it = 0; it < 4; it++) {
        int f = it * 128 + tid, row = f >> 3, c8 = (f & 7) << 3;
        size_t src = ((size_t)(b * S_ + q0 + row) * H_ + h) * HD_ + c8;
        *(uint4*)&Kh[1][row * TSTR + c8] = *(const uint4*)(qh_g + src);
        *(uint4*)&Vh[1][row * TSTR + c8] = *(const uint4*)(ql_g + src);
    }
    __syncthreads();

    uint32 qh[4][4], ql[4][4];
    #pragma unroll
    for (int kc = 0; kc < 4; kc++) {
        int off = (warp * 16 + a_lr) * TSTR + kc * 16 + a_k8;
        ldsm4(qh[kc][0], qh[kc][1], qh[kc][2], qh[kc][3], &Kh[1][off]);
        ldsm4(ql[kc][0], ql[kc][1], ql[kc][2], ql[kc][3], &Vh[1][off]);
    }
    // no sync needed: buffer 1 first overwritten by tile 1, whose stores come
    // after tile 0's sync, which follows these ldsm in program order.

    float octx[8][4];
    #pragma unroll
    for (int i = 0; i < 8; i++)
        #pragma unroll
        for (int j = 0; j < 4; j++) octx[i][j] = 0.f;
    float m0 = NEG_BIG, m1 = NEG_BIG, l0 = 0.f, l1 = 0.f;

    const int ntiles = qt + 1;
    for (int t = 0; t < ntiles; t++) {
        const int kt0 = t * 64;
        const int bf  = t & 1;
        __half* Kb = Kh[bf];
        __half* Vb = Vh[bf];

        // ---- K/V tiles (512 chunks of 8 halves each) ----
        #pragma unroll
        for (int it = 0; it < 4; it++) {
            int f = it * 128 + tid, row = f >> 3, c8 = (f & 7) << 3;
            size_t src = ((size_t)(b * S_ + kt0 + row) * G_ + g) * HD_ + c8;
            *(uint4*)&Kb[row * TSTR + c8] = *(const uint4*)(kh_g + src);
            *(uint4*)&Vb[row * TSTR + c8] = *(const uint4*)(vh_g + src);
        }
        __syncthreads();   // the ONLY barrier per tile

        float sc[8][4];
        #pragma unroll
        for (int i = 0; i < 8; i++)
            #pragma unroll
            for (int j = 0; j < 4; j++) sc[i][j] = 0.f;

        // ---- Scores: hi term fp32-accum, lo correction fp16-accum ----
        #pragma unroll
        for (int kg = 0; kg < 4; kg++) {
            uint32 scl0[2] = {0u, 0u}, scl1[2] = {0u, 0u};
            #pragma unroll
            for (int kc = 0; kc < 4; kc++) {
                uint32 bh0, bh1, bh2, bh3;
                int off = (kg * 16 + b_nr) * TSTR + kc * 16 + b_k8;
                ldsm4(bh0, bh1, bh2, bh3, &Kb[off]);
                mma16816h(sc[2*kg],    qh[kc], bh0, bh1);
                mma16816hh(scl0,       ql[kc], bh0, bh1);
                mma16816h(sc[2*kg+1],  qh[kc], bh2, bh3);
                mma16816hh(scl1,       ql[kc], bh2, bh3);
            }
            addh2(sc[2*kg][0],   sc[2*kg][1],   scl0[0]);
            addh2(sc[2*kg][2],   sc[2*kg][3],   scl0[1]);
            addh2(sc[2*kg+1][0], sc[2*kg+1][1], scl1[0]);
            addh2(sc[2*kg+1][2], sc[2*kg+1][3], scl1[1]);
        }

        const int gq = lane >> 2, tt = lane & 3;
        if (kt0 == q0) {
            int qi0 = q0 + warp * 16 + gq;
            int qi1 = qi0 + 8;
            #pragma unroll
            for (int j = 0; j < 8; j++) {
                int kj = kt0 + j * 8 + tt * 2;
                if (kj     > qi0) sc[j][0] = NEG_BIG;
                if (kj + 1 > qi0) sc[j][1] = NEG_BIG;
                if (kj     > qi1) sc[j][2] = NEG_BIG;
                if (kj + 1 > qi1) sc[j][3] = NEG_BIG;
            }
        }

        float mx0 = NEG_BIG, mx1 = NEG_BIG;
        #pragma unroll
        for (int j = 0; j < 8; j++) {
            mx0 = fmaxf(mx0, fmaxf(sc[j][0], sc[j][1]));
            mx1 = fmaxf(mx1, fmaxf(sc[j][2], sc[j][3]));
        }
        #pragma unroll
        for (int o = 1; o <= 2; o <<= 1) {
            mx0 = fmaxf(mx0, __shfl_xor_sync(0xffffffffu, mx0, o));
            mx1 = fmaxf(mx1, __shfl_xor_sync(0xffffffffu, mx1, o));
        }
        mx0 = fmaxf(mx0, m0); mx1 = fmaxf(mx1, m1);
        float alpha0 = __expf(m0 - mx0), alpha1 = __expf(m1 - mx1);
        m0 = mx0; m1 = mx1;

        float s0 = 0.f, s1 = 0.f;
        #pragma unroll
        for (int j = 0; j < 8; j++) {
            sc[j][0] = __expf(sc[j][0] - m0); s0 += sc[j][0];
            sc[j][1] = __expf(sc[j][1] - m0); s0 += sc[j][1];
            sc[j][2] = __expf(sc[j][2] - m1); s1 += sc[j][2];
            sc[j][3] = __expf(sc[j][3] - m1); s1 += sc[j][3];
        }
        #pragma unroll
        for (int o = 1; o <= 2; o <<= 1) {
            s0 += __shfl_xor_sync(0xffffffffu, s0, o);
            s1 += __shfl_xor_sync(0xffffffffu, s1, o);
        }
        l0 = l0 * alpha0 + s0;
        l1 = l1 * alpha1 + s1;

        #pragma unroll
        for (int ni = 0; ni < 8; ni++) {
            octx[ni][0] *= alpha0; octx[ni][1] *= alpha0;
            octx[ni][2] *= alpha1; octx[ni][3] *= alpha1;
        }

        uint32 aph[4][4], apl[4][4];
        #pragma unroll
        for (int kc = 0; kc < 4; kc++) {
            split2h(sc[2*kc][0],   sc[2*kc][1],   aph[kc][0], apl[kc][0]);
            split2h(sc[2*kc][2],   sc[2*kc][3],   aph[kc][1], apl[kc][1]);
            split2h(sc[2*kc+1][0], sc[2*kc+1][1], aph[kc][2], apl[kc][2]);
            split2h(sc[2*kc+1][2], sc[2*kc+1][3], aph[kc][3], apl[kc][3]);
        }

        // ---- ctx: Ph·V fp32-accum, Pl·V correction fp16-accum ----
        #pragma unroll
        for (int ni = 0; ni < 8; ni++) {
            uint32 ocl[2] = {0u, 0u};
            #pragma unroll
            for (int kc = 0; kc < 4; kc++) {
                uint32 vh0, vh1;
                int off = (kc * 16 + v_r) * TSTR + ni * 8;
                ldsm2t(vh0, vh1, &Vb[off]);
                mma16816h(octx[ni], aph[kc], vh0, vh1);
                mma16816hh(ocl,     apl[kc], vh0, vh1);
            }
            addh2(octx[ni][0], octx[ni][1], ocl[0]);
            addh2(octx[ni][2], octx[ni][3], ocl[1]);
        }
        // no trailing sync — next tile writes the other buffer
    }

    const int gq = lane >> 2, tt = lane & 3;
    float inv0 = 1.0f / l0, inv1 = 1.0f / l1;
    #pragma unroll
    for (int ni = 0; ni < 8; ni++) {
        int row = q0 + warp * 16 + gq;
        int col = ni * 8 + tt * 2;
        *(float2*)(ctx + (((size_t)(b * S_ + row)) * H_ + h) * HD_ + col) =
            make_float2(octx[ni][0] * inv0, octx[ni][1] * inv0);
        *(float2*)(ctx + (((size_t)(b * S_ + row + 8)) * H_ + h) * HD_ + col) =
            make_float2(octx[ni][2] * inv1, octx[ni][3] * inv1);
    }
}

// ---------------------------------------------------------------------------
// Launch
// ---------------------------------------------------------------------------
extern "C" void kernel_launch(void* const* d_in, const int* in_sizes, int n_in,
                              void* d_out, int out_size)
{
    (void)in_sizes; (void)n_in; (void)out_size;
    const float* x    = (const float*)d_in[0];
    const float* cosp = (const float*)d_in[2];
    const float* sinp = (const float*)d_in[3];
    const float* Wq   = (const float*)d_in[4];
    const float* Wk   = (const float*)d_in[5];
    const float* Wv   = (const float*)d_in[6];
    const float* Wo   = (const float*)d_in[7];
    const float* qsc  = (const float*)d_in[8];
    const float* ksc  = (const float*)d_in[9];
    float* out = (float*)d_out;

    float *pq, *pk, *pc;
    __half *pqh, *pql, *pkh, *pvh;
    cudaGetSymbolAddress((void**)&pq, g_q);
    cudaGetSymbolAddress((void**)&pk, g_k);
    cudaGetSymbolAddress((void**)&pc, g_ctx);
    cudaGetSymbolAddress((void**)&pqh, g_qh);
    cudaGetSymbolAddress((void**)&pql, g_ql);
    cudaGetSymbolAddress((void**)&pkh, g_kh);
    cudaGetSymbolAddress((void**)&pvh, g_vh);

    static bool attr_done = false;
    if (!attr_done) {
        cudaFuncSetAttribute(gemm_qkv, cudaFuncAttributeMaxDynamicSharedMemorySize, SMEM_BYTES);
        cudaFuncSetAttribute(gemm_o,   cudaFuncAttributeMaxDynamicSharedMemorySize, SMEM_BYTES);
        attr_done = true;
    }

    // weights -> fp16 (once per launch)
    wconv<<<(WTOT4 + 255) / 256, 256>>>(Wq, Wk, Wv, Wo);

    // merged QKV projection (v written fp16 directly)
    gemm_qkv<<<dim3(48, M_/BM), 256, SMEM_BYTES>>>(x);

    // rmsnorm + rope -> fp16 (q: hi+lo, k: hi only)
    rms_rope_h<<<(M_*H_)/8, 256>>>(pq, pqh, pql, cosp, sinp, qsc, H_, 0.125f, 1);
    rms_rope_h<<<(M_*G_)/8, 256>>>(pk, pkh, nullptr, cosp, sinp, ksc, G_, 1.0f, 0);

    // attention (fp16 inputs, longest-first, fp16-accum lo corrections)
    attn_tc<<<dim3(S_/64, H_, B_), 128>>>(pqh, pql, pkh, pvh, pc);

    // output projection
    gemm_o<<<dim3(D_/BN, M_/BM), 256, SMEM_BYTES>>>(out);
}

// round 16
// speedup vs baseline: 1.0292x; 1.0292x over previous
#include <cuda_runtime.h>
#include <cuda_fp16.h>
#include <math.h>

#define B_ 2
#define S_ 2048
#define D_ 2048
#define H_ 32
#define G_ 8
#define HD_ 64
#define GS_ (H_/G_)
#define M_ (B_*S_)

typedef unsigned int uint32;

// ---- tensor-core helpers (fp16 path) ----
__device__ __forceinline__ void ldsm4(uint32 &r0, uint32 &r1, uint32 &r2, uint32 &r3,
                                      const void* p) {
    uint32 a = (uint32)__cvta_generic_to_shared(p);
    asm volatile("ldmatrix.sync.aligned.m8n8.x4.shared.b16 {%0,%1,%2,%3},[%4];"
                 : "=r"(r0), "=r"(r1), "=r"(r2), "=r"(r3) : "r"(a));
}
__device__ __forceinline__ void ldsm2t(uint32 &r0, uint32 &r1, const void* p) {
    uint32 a = (uint32)__cvta_generic_to_shared(p);
    asm volatile("ldmatrix.sync.aligned.m8n8.x2.trans.shared.b16 {%0,%1},[%2];"
                 : "=r"(r0), "=r"(r1) : "r"(a));
}
__device__ __forceinline__ void mma16816h(float c[4], const uint32 a[4],
                                          uint32 b0, uint32 b1) {
    asm volatile(
        "mma.sync.aligned.m16n8k16.row.col.f32.f16.f16.f32 "
        "{%0,%1,%2,%3},{%4,%5,%6,%7},{%8,%9},{%0,%1,%2,%3};"
        : "+f"(c[0]), "+f"(c[1]), "+f"(c[2]), "+f"(c[3])
        : "r"(a[0]), "r"(a[1]), "r"(a[2]), "r"(a[3]), "r"(b0), "r"(b1));
}
__device__ __forceinline__ void split2h(float p0, float p1, uint32 &h, uint32 &l) {
    __half2 hh = __floats2half2_rn(p0, p1);
    float2 hf = __half22float2(hh);
    __half2 ll = __floats2half2_rn(p0 - hf.x, p1 - hf.y);
    h = *(uint32*)&hh;
    l = *(uint32*)&ll;
}
__device__ __forceinline__ uint32 pack2h(float p0, float p1) {
    __half2 hh = __floats2half2_rn(p0, p1);
    return *(uint32*)&hh;
}
__device__ __forceinline__ void cvt4h(float4 v, uint2 &hi, uint2 &lo) {
    split2h(v.x, v.y, hi.x, lo.x);
    split2h(v.z, v.w, hi.y, lo.y);
}
__device__ __forceinline__ uint2 cvt4h1(float4 v) {
    return make_uint2(pack2h(v.x, v.y), pack2h(v.z, v.w));
}

// ---- Scratch ----
__device__ float g_q[(size_t)M_*H_*HD_];
__device__ float g_k[(size_t)M_*G_*HD_];
__device__ float g_ctx[(size_t)M_*H_*HD_];
__device__ __half g_wqh[(size_t)H_*HD_*D_];
__device__ __half g_wkh[(size_t)G_*HD_*D_];
__device__ __half g_wvh[(size_t)G_*HD_*D_];
__device__ __half g_woh[(size_t)D_*H_*HD_];
__device__ __half g_qh[(size_t)M_*H_*HD_], g_ql[(size_t)M_*H_*HD_];
__device__ __half g_kh[(size_t)M_*G_*HD_];
__device__ __half g_vh[(size_t)M_*G_*HD_];

// ---------------------------------------------------------------------------
// Weight fp32 -> fp16 conversion (one pass over Wq|Wk|Wv|Wo)
// ---------------------------------------------------------------------------
#define WQ4 1048576u
#define WK4 262144u
#define WV4 262144u
#define WO4 1048576u
#define WTOT4 (WQ4+WK4+WV4+WO4)

__global__ __launch_bounds__(256) void wconv(
    const float* __restrict__ Wq, const float* __restrict__ Wk,
    const float* __restrict__ Wv, const float* __restrict__ Wo)
{
    uint32 i = blockIdx.x * 256 + threadIdx.x;
    if (i >= WTOT4) return;
    const float* src; __half* dst; uint32 off;
    if (i < WQ4)                   { src = Wq; dst = g_wqh; off = i; }
    else if (i < WQ4 + WK4)        { src = Wk; dst = g_wkh; off = i - WQ4; }
    else if (i < WQ4 + WK4 + WV4)  { src = Wv; dst = g_wvh; off = i - WQ4 - WK4; }
    else                           { src = Wo; dst = g_woh; off = i - WQ4 - WK4 - WV4; }
    float4 v = ((const float4*)src)[off];
    ((uint2*)dst)[off] = cvt4h1(v);
}

// ---------------------------------------------------------------------------
// NT GEMM: A fp32 (split hi/lo in-kernel), B fp16 pre-converted. (R14 frozen)
// ---------------------------------------------------------------------------
#define BM 128
#define BN 64
#define BKK 32
#define ASTR 40
#define STAGE_ELEMS (BM*ASTR*2 + BN*ASTR)
#define SMEM_BYTES  (2 * STAGE_ELEMS * 2)

__device__ __forceinline__ void gemm_body(
    const float* __restrict__ A, const __half* __restrict__ Bg,
    float* __restrict__ Cf, __half* __restrict__ Ch,
    int N, int K, int m0, int n0, __half* sm)
{
    const int tid  = threadIdx.x;
    const int lane = tid & 31;
    const int warp = tid >> 5;
    const int wm = (warp >> 1) * 32;
    const int wn = (warp & 1) * 32;

    const int a_lr = lane & 15;
    const int a_k8 = ((lane >> 4) & 1) << 3;
    const int b_nr = (((lane >> 4) & 1) << 3) | (lane & 7);
    const int b_k8 = ((lane >> 3) & 1) << 3;

    float acc[2][4][4];
    #pragma unroll
    for (int i = 0; i < 2; i++)
        #pragma unroll
        for (int j = 0; j < 4; j++)
            #pragma unroll
            for (int t = 0; t < 4; t++) acc[i][j][t] = 0.f;

    const int b_row = tid >> 2, b_c8 = (tid & 3) << 3;
    float4 ar[4]; uint4 br;
    #pragma unroll
    for (int it = 0; it < 4; it++) {
        int f = it * 256 + tid, row = f >> 3, c4 = f & 7;
        ar[it] = *(const float4*)(A + (size_t)(m0 + row) * K + c4 * 4);
    }
    br = *(const uint4*)(Bg + (size_t)(n0 + b_row) * K + b_c8);

    for (int kb = 0; kb < K; kb += BKK) {
        const int st = (kb >> 5) & 1;
        __half* Ah = sm + st * STAGE_ELEMS;
        __half* Al = Ah + BM * ASTR;
        __half* Bh = Al + BM * ASTR;

        #pragma unroll
        for (int it = 0; it < 4; it++) {
            int f = it * 256 + tid, row = f >> 3, c4 = f & 7;
            uint2 hi, lo; cvt4h(ar[it], hi, lo);
            *(uint2*)&Ah[row * ASTR + c4 * 4] = hi;
            *(uint2*)&Al[row * ASTR + c4 * 4] = lo;
        }
        *(uint4*)&Bh[b_row * ASTR + b_c8] = br;
        __syncthreads();

        if (kb + BKK < K) {
            #pragma unroll
            for (int it = 0; it < 4; it++) {
                int f = it * 256 + tid, row = f >> 3, c4 = f & 7;
                ar[it] = *(const float4*)(A + (size_t)(m0 + row) * K + kb + BKK + c4 * 4);
            }
            br = *(const uint4*)(Bg + (size_t)(n0 + b_row) * K + kb + BKK + b_c8);
        }

        #pragma unroll
        for (int ks = 0; ks < BKK; ks += 16) {
            uint32 ah[2][4], al[2][4], bh[2][4];
            #pragma unroll
            for (int mi = 0; mi < 2; mi++) {
                int off = (wm + mi * 16 + a_lr) * ASTR + ks + a_k8;
                ldsm4(ah[mi][0], ah[mi][1], ah[mi][2], ah[mi][3], &Ah[off]);
                ldsm4(al[mi][0], al[mi][1], al[mi][2], al[mi][3], &Al[off]);
            }
            #pragma unroll
            for (int p = 0; p < 2; p++) {
                int off = (wn + p * 16 + b_nr) * ASTR + ks + b_k8;
                ldsm4(bh[p][0], bh[p][1], bh[p][2], bh[p][3], &Bh[off]);
            }
            #pragma unroll
            for (int mi = 0; mi < 2; mi++)
                #pragma unroll
                for (int ni = 0; ni < 4; ni++) {
                    int p = ni >> 1, s = (ni & 1) * 2;
                    mma16816h(acc[mi][ni], ah[mi], bh[p][s], bh[p][s+1]);
                    mma16816h(acc[mi][ni], al[mi], bh[p][s], bh[p][s+1]);
                }
        }
    }

    const int gq = lane >> 2, t = lane & 3;
    if (Ch) {
        #pragma unroll
        for (int mi = 0; mi < 2; mi++)
            #pragma unroll
            for (int ni = 0; ni < 4; ni++) {
                int row = m0 + wm + mi * 16 + gq;
                int col = n0 + wn + ni * 8 + t * 2;
                *(uint32*)(Ch + (size_t)row * N + col) =
                    pack2h(acc[mi][ni][0], acc[mi][ni][1]);
                *(uint32*)(Ch + (size_t)(row + 8) * N + col) =
                    pack2h(acc[mi][ni][2], acc[mi][ni][3]);
            }
    } else {
        #pragma unroll
        for (int mi = 0; mi < 2; mi++)
            #pragma unroll
            for (int ni = 0; ni < 4; ni++) {
                int row = m0 + wm + mi * 16 + gq;
                int col = n0 + wn + ni * 8 + t * 2;
                *(float2*)(Cf + (size_t)row * N + col)       = make_float2(acc[mi][ni][0], acc[mi][ni][1]);
                *(float2*)(Cf + (size_t)(row + 8) * N + col) = make_float2(acc[mi][ni][2], acc[mi][ni][3]);
            }
    }
}

__global__ __launch_bounds__(256, 2) void gemm_qkv(const float* __restrict__ x)
{
    extern __shared__ __half sm[];
    int nb = blockIdx.x;
    if (nb < 32)
        gemm_body(x, g_wqh, g_q, nullptr, H_*HD_, D_, blockIdx.y * BM, nb * 64, sm);
    else if (nb < 40)
        gemm_body(x, g_wkh, g_k, nullptr, G_*HD_, D_, blockIdx.y * BM, (nb - 32) * 64, sm);
    else
        gemm_body(x, g_wvh, nullptr, g_vh, G_*HD_, D_, blockIdx.y * BM, (nb - 40) * 64, sm);
}

__global__ __launch_bounds__(256, 2) void gemm_o(float* __restrict__ out)
{
    extern __shared__ __half sm[];
    gemm_body(g_ctx, g_woh, out, nullptr, D_, H_*HD_, blockIdx.y * BM, blockIdx.x * 64, sm);
}

// ---------------------------------------------------------------------------
// Fused RMSNorm + RoPE + scale, emitting fp16 (hi, optional lo). (R14 frozen)
// ---------------------------------------------------------------------------
__global__ __launch_bounds__(256) void rms_rope_h(
    const float* __restrict__ t, __half* __restrict__ th, __half* __restrict__ tl,
    const float* __restrict__ cosp, const float* __restrict__ sinp,
    const float* __restrict__ scale, int NH, float mul, int wlo)
{
    const int warp = (blockIdx.x * blockDim.x + threadIdx.x) >> 5;
    const int lane = threadIdx.x & 31;
    const int s = (warp / NH) % S_;
    const float* p = t + (size_t)warp * HD_;

    float t1 = p[lane];
    float t2 = p[lane + 32];
    float ss = t1 * t1 + t2 * t2;
    #pragma unroll
    for (int o = 16; o > 0; o >>= 1) ss += __shfl_xor_sync(0xffffffffu, ss, o);
    float rs = rsqrtf(ss * (1.0f / HD_) + 1e-6f);

    float n1 = t1 * rs * (1.0f + scale[lane]);
    float n2 = t2 * rs * (1.0f + scale[lane + 32]);

    float c1 = cosp[s * HD_ + lane],      c2 = cosp[s * HD_ + lane + 32];
    float s1 = sinp[s * HD_ + lane],      s2 = sinp[s * HD_ + lane + 32];
    float o1 = (n1 * c1 - n2 * s1) * mul;
    float o2 = (n2 * c2 + n1 * s2) * mul;

    size_t base = (size_t)warp * HD_;
    __half h1 = __float2half_rn(o1);
    __half h2 = __float2half_rn(o2);
    th[base + lane]      = h1;
    th[base + lane + 32] = h2;
    if (wlo) {
        tl[base + lane]      = __float2half_rn(o1 - __half2float(h1));
        tl[base + lane + 32] = __float2half_rn(o2 - __half2float(h2));
    }
}

// ---------------------------------------------------------------------------
// Tensor-core causal flash attention. fp16 inputs, double-buffered K/V,
// ONE sync/tile, longest-first. Register diet: P fragments built per-kc
// inside the PV loop (kc-outer). Forced 4 CTAs/SM for 16 warps.
// ---------------------------------------------------------------------------
#define TSTR 72
#define NEG_BIG (-1e30f)

__global__ __launch_bounds__(128, 4) void attn_tc(
    const __half* __restrict__ qh_g, const __half* __restrict__ ql_g,
    const __half* __restrict__ kh_g, const __half* __restrict__ vh_g,
    float* __restrict__ ctx)
{
    __shared__ __align__(16) __half Kh[2][64*TSTR];
    __shared__ __align__(16) __half Vh[2][64*TSTR];

    const int tid  = threadIdx.x;
    const int lane = tid & 31;
    const int warp = tid >> 5;
    const int qt = (S_/64 - 1) - blockIdx.x;   // longest-first
    const int h  = blockIdx.y, b = blockIdx.z;
    const int g  = h / GS_;
    const int q0 = qt * 64;

    const int a_lr = lane & 15;
    const int a_k8 = ((lane >> 4) & 1) << 3;
    const int b_nr = (((lane >> 4) & 1) << 3) | (lane & 7);
    const int b_k8 = ((lane >> 3) & 1) << 3;
    const int v_r  = lane & 15;

    // ---- Q tile: hi into Kh[1], lo into Vh[1] (512 chunks of 8 halves) ----
    #pragma unroll
    for (int it = 0; it < 4; it++) {
        int f = it * 128 + tid, row = f >> 3, c8 = (f & 7) << 3;
        size_t src = ((size_t)(b * S_ + q0 + row) * H_ + h) * HD_ + c8;
        *(uint4*)&Kh[1][row * TSTR + c8] = *(const uint4*)(qh_g + src);
        *(uint4*)&Vh[1][row * TSTR + c8] = *(const uint4*)(ql_g + src);
    }
    __syncthreads();

    uint32 qh[4][4], ql[4][4];
    #pragma unroll
    for (int kc = 0; kc < 4; kc++) {
        int off = (warp * 16 + a_lr) * TSTR + kc * 16 + a_k8;
        ldsm4(qh[kc][0], qh[kc][1], qh[kc][2], qh[kc][3], &Kh[1][off]);
        ldsm4(ql[kc][0], ql[kc][1], ql[kc][2], ql[kc][3], &Vh[1][off]);
    }
    // no sync needed: buffer 1 first overwritten by tile 1, whose stores come
    // after tile 0's sync, which follows these ldsm in program order.

    float octx[8][4];
    #pragma unroll
    for (int i = 0; i < 8; i++)
        #pragma unroll
        for (int j = 0; j < 4; j++) octx[i][j] = 0.f;
    float m0 = NEG_BIG, m1 = NEG_BIG, l0 = 0.f, l1 = 0.f;

    const int ntiles = qt + 1;
    for (int t = 0; t < ntiles; t++) {
        const int kt0 = t * 64;
        const int bf  = t & 1;
        __half* Kb = Kh[bf];
        __half* Vb = Vh[bf];

        // ---- K/V tiles (512 chunks of 8 halves each) ----
        #pragma unroll
        for (int it = 0; it < 4; it++) {
            int f = it * 128 + tid, row = f >> 3, c8 = (f & 7) << 3;
            size_t src = ((size_t)(b * S_ + kt0 + row) * G_ + g) * HD_ + c8;
            *(uint4*)&Kb[row * TSTR + c8] = *(const uint4*)(kh_g + src);
            *(uint4*)&Vb[row * TSTR + c8] = *(const uint4*)(vh_g + src);
        }
        __syncthreads();   // the ONLY barrier per tile

        float sc[8][4];
        #pragma unroll
        for (int i = 0; i < 8; i++)
            #pragma unroll
            for (int j = 0; j < 4; j++) sc[i][j] = 0.f;

        #pragma unroll
        for (int kg = 0; kg < 4; kg++) {
            #pragma unroll
            for (int kc = 0; kc < 4; kc++) {
                uint32 bh0, bh1, bh2, bh3;
                int off = (kg * 16 + b_nr) * TSTR + kc * 16 + b_k8;
                ldsm4(bh0, bh1, bh2, bh3, &Kb[off]);
                mma16816h(sc[2*kg],   qh[kc], bh0, bh1);
                mma16816h(sc[2*kg],   ql[kc], bh0, bh1);
                mma16816h(sc[2*kg+1], qh[kc], bh2, bh3);
                mma16816h(sc[2*kg+1], ql[kc], bh2, bh3);
            }
        }

        const int gq = lane >> 2, tt = lane & 3;
        if (kt0 == q0) {
            int qi0 = q0 + warp * 16 + gq;
            int qi1 = qi0 + 8;
            #pragma unroll
            for (int j = 0; j < 8; j++) {
                int kj = kt0 + j * 8 + tt * 2;
                if (kj     > qi0) sc[j][0] = NEG_BIG;
                if (kj + 1 > qi0) sc[j][1] = NEG_BIG;
                if (kj     > qi1) sc[j][2] = NEG_BIG;
                if (kj + 1 > qi1) sc[j][3] = NEG_BIG;
            }
        }

        float mx0 = NEG_BIG, mx1 = NEG_BIG;
        #pragma unroll
        for (int j = 0; j < 8; j++) {
            mx0 = fmaxf(mx0, fmaxf(sc[j][0], sc[j][1]));
            mx1 = fmaxf(mx1, fmaxf(sc[j][2], sc[j][3]));
        }
        #pragma unroll
        for (int o = 1; o <= 2; o <<= 1) {
            mx0 = fmaxf(mx0, __shfl_xor_sync(0xffffffffu, mx0, o));
            mx1 = fmaxf(mx1, __shfl_xor_sync(0xffffffffu, mx1, o));
        }
        mx0 = fmaxf(mx0, m0); mx1 = fmaxf(mx1, m1);
        float alpha0 = __expf(m0 - mx0), alpha1 = __expf(m1 - mx1);
        m0 = mx0; m1 = mx1;

        float s0 = 0.f, s1 = 0.f;
        #pragma unroll
        for (int j = 0; j < 8; j++) {
            sc[j][0] = __expf(sc[j][0] - m0); s0 += sc[j][0];
            sc[j][1] = __expf(sc[j][1] - m0); s0 += sc[j][1];
            sc[j][2] = __expf(sc[j][2] - m1); s1 += sc[j][2];
            sc[j][3] = __expf(sc[j][3] - m1); s1 += sc[j][3];
        }
        #pragma unroll
        for (int o = 1; o <= 2; o <<= 1) {
            s0 += __shfl_xor_sync(0xffffffffu, s0, o);
            s1 += __shfl_xor_sync(0xffffffffu, s1, o);
        }
        l0 = l0 * alpha0 + s0;
        l1 = l1 * alpha1 + s1;

        #pragma unroll
        for (int ni = 0; ni < 8; ni++) {
            octx[ni][0] *= alpha0; octx[ni][1] *= alpha0;
            octx[ni][2] *= alpha1; octx[ni][3] *= alpha1;
        }

        // ---- ctx += (Ph + Pl) @ V — kc outer, P fragments per-kc ----
        #pragma unroll
        for (int kc = 0; kc < 4; kc++) {
            uint32 aph[4], apl[4];
            split2h(sc[2*kc][0],   sc[2*kc][1],   aph[0], apl[0]);
            split2h(sc[2*kc][2],   sc[2*kc][3],   aph[1], apl[1]);
            split2h(sc[2*kc+1][0], sc[2*kc+1][1], aph[2], apl[2]);
            split2h(sc[2*kc+1][2], sc[2*kc+1][3], aph[3], apl[3]);
            #pragma unroll
            for (int ni = 0; ni < 8; ni++) {
                uint32 vh0, vh1;
                int off = (kc * 16 + v_r) * TSTR + ni * 8;
                ldsm2t(vh0, vh1, &Vb[off]);
                mma16816h(octx[ni], aph, vh0, vh1);
                mma16816h(octx[ni], apl, vh0, vh1);
            }
        }
        // no trailing sync — next tile writes the other buffer
    }

    const int gq = lane >> 2, tt = lane & 3;
    float inv0 = 1.0f / l0, inv1 = 1.0f / l1;
    #pragma unroll
    for (int ni = 0; ni < 8; ni++) {
        int row = q0 + warp * 16 + gq;
        int col = ni * 8 + tt * 2;
        *(float2*)(ctx + (((size_t)(b * S_ + row)) * H_ + h) * HD_ + col) =
            make_float2(octx[ni][0] * inv0, octx[ni][1] * inv0);
        *(float2*)(ctx + (((size_t)(b * S_ + row + 8)) * H_ + h) * HD_ + col) =
            make_float2(octx[ni][2] * inv1, octx[ni][3] * inv1);
    }
}

// ---------------------------------------------------------------------------
// Launch
// ---------------------------------------------------------------------------
extern "C" void kernel_launch(void* const* d_in, const int* in_sizes, int n_in,
                              void* d_out, int out_size)
{
    (void)in_sizes; (void)n_in; (void)out_size;
    const float* x    = (const float*)d_in[0];
    const float* cosp = (const float*)d_in[2];
    const float* sinp = (const float*)d_in[3];
    const float* Wq   = (const float*)d_in[4];
    const float* Wk   = (const float*)d_in[5];
    const float* Wv   = (const float*)d_in[6];
    const float* Wo   = (const float*)d_in[7];
    const float* qsc  = (const float*)d_in[8];
    const float* ksc  = (const float*)d_in[9];
    float* out = (float*)d_out;

    float *pq, *pk, *pc;
    __half *pqh, *pql, *pkh, *pvh;
    cudaGetSymbolAddress((void**)&pq, g_q);
    cudaGetSymbolAddress((void**)&pk, g_k);
    cudaGetSymbolAddress((void**)&pc, g_ctx);
    cudaGetSymbolAddress((void**)&pqh, g_qh);
    cudaGetSymbolAddress((void**)&pql, g_ql);
    cudaGetSymbolAddress((void**)&pkh, g_kh);
    cudaGetSymbolAddress((void**)&pvh, g_vh);

    static bool attr_done = false;
    if (!attr_done) {
        cudaFuncSetAttribute(gemm_qkv, cudaFuncAttributeMaxDynamicSharedMemorySize, SMEM_BYTES);
        cudaFuncSetAttribute(gemm_o,   cudaFuncAttributeMaxDynamicSharedMemorySize, SMEM_BYTES);
        attr_done = true;
    }

    // weights -> fp16 (once per launch)
    wconv<<<(WTOT4 + 255) / 256, 256>>>(Wq, Wk, Wv, Wo);

    // merged QKV projection (v written fp16 directly)
    gemm_qkv<<<dim3(48, M_/BM), 256, SMEM_BYTES>>>(x);

    // rmsnorm + rope -> fp16 (q: hi+lo, k: hi only)
    rms_rope_h<<<(M_*H_)/8, 256>>>(pq, pqh, pql, cosp, sinp, qsc, H_, 0.125f, 1);
    rms_rope_h<<<(M_*G_)/8, 256>>>(pk, pkh, nullptr, cosp, sinp, ksc, G_, 1.0f, 0);

    // attention (fp16 inputs, longest-first, 4 CTAs/SM)
    attn_tc<<<dim3(S_/64, H_, B_), 128>>>(pqh, pql, pkh, pvh, pc);

    // output projection
    gemm_o<<<dim3(D_/BN, M_/BM), 256, SMEM_BYTES>>>(out);
}

// round 17
// speedup vs baseline: 1.1605x; 1.1277x over previous
#include <cuda_runtime.h>
#include <cuda_fp16.h>
#include <math.h>

#define B_ 2
#define S_ 2048
#define D_ 2048
#define H_ 32
#define G_ 8
#define HD_ 64
#define GS_ (H_/G_)
#define M_ (B_*S_)

typedef unsigned int uint32;

// ---- tensor-core helpers (fp16 path) ----
__device__ __forceinline__ void ldsm4(uint32 &r0, uint32 &r1, uint32 &r2, uint32 &r3,
                                      const void* p) {
    uint32 a = (uint32)__cvta_generic_to_shared(p);
    asm volatile("ldmatrix.sync.aligned.m8n8.x4.shared.b16 {%0,%1,%2,%3},[%4];"
                 : "=r"(r0), "=r"(r1), "=r"(r2), "=r"(r3) : "r"(a));
}
__device__ __forceinline__ void ldsm2t(uint32 &r0, uint32 &r1, const void* p) {
    uint32 a = (uint32)__cvta_generic_to_shared(p);
    asm volatile("ldmatrix.sync.aligned.m8n8.x2.trans.shared.b16 {%0,%1},[%2];"
                 : "=r"(r0), "=r"(r1) : "r"(a));
}
__device__ __forceinline__ void mma16816h(float c[4], const uint32 a[4],
                                          uint32 b0, uint32 b1) {
    asm volatile(
        "mma.sync.aligned.m16n8k16.row.col.f32.f16.f16.f32 "
        "{%0,%1,%2,%3},{%4,%5,%6,%7},{%8,%9},{%0,%1,%2,%3};"
        : "+f"(c[0]), "+f"(c[1]), "+f"(c[2]), "+f"(c[3])
        : "r"(a[0]), "r"(a[1]), "r"(a[2]), "r"(a[3]), "r"(b0), "r"(b1));
}
__device__ __forceinline__ void split2h(float p0, float p1, uint32 &h, uint32 &l) {
    __half2 hh = __floats2half2_rn(p0, p1);
    float2 hf = __half22float2(hh);
    __half2 ll = __floats2half2_rn(p0 - hf.x, p1 - hf.y);
    h = *(uint32*)&hh;
    l = *(uint32*)&ll;
}
__device__ __forceinline__ uint32 pack2h(float p0, float p1) {
    __half2 hh = __floats2half2_rn(p0, p1);
    return *(uint32*)&hh;
}
__device__ __forceinline__ void cvt4h(float4 v, uint2 &hi, uint2 &lo) {
    split2h(v.x, v.y, hi.x, lo.x);
    split2h(v.z, v.w, hi.y, lo.y);
}
__device__ __forceinline__ uint2 cvt4h1(float4 v) {
    return make_uint2(pack2h(v.x, v.y), pack2h(v.z, v.w));
}

// ---- Scratch ----
__device__ float g_q[(size_t)M_*H_*HD_];
__device__ float g_k[(size_t)M_*G_*HD_];
__device__ __half g_wqh[(size_t)H_*HD_*D_];
__device__ __half g_wkh[(size_t)G_*HD_*D_];
__device__ __half g_wvh[(size_t)G_*HD_*D_];
__device__ __half g_woh[(size_t)D_*H_*HD_];
__device__ __half g_qh[(size_t)M_*H_*HD_], g_ql[(size_t)M_*H_*HD_];
__device__ __half g_kh[(size_t)M_*G_*HD_];
__device__ __half g_vh[(size_t)M_*G_*HD_];
__device__ __half g_cth[(size_t)M_*H_*HD_];   // ctx fp16 (attention output)

// ---------------------------------------------------------------------------
// Weight fp32 -> fp16 conversion (one pass over Wq|Wk|Wv|Wo)
// ---------------------------------------------------------------------------
#define WQ4 1048576u
#define WK4 262144u
#define WV4 262144u
#define WO4 1048576u
#define WTOT4 (WQ4+WK4+WV4+WO4)

__global__ __launch_bounds__(256) void wconv(
    const float* __restrict__ Wq, const float* __restrict__ Wk,
    const float* __restrict__ Wv, const float* __restrict__ Wo)
{
    uint32 i = blockIdx.x * 256 + threadIdx.x;
    if (i >= WTOT4) return;
    const float* src; __half* dst; uint32 off;
    if (i < WQ4)                   { src = Wq; dst = g_wqh; off = i; }
    else if (i < WQ4 + WK4)        { src = Wk; dst = g_wkh; off = i - WQ4; }
    else if (i < WQ4 + WK4 + WV4)  { src = Wv; dst = g_wvh; off = i - WQ4 - WK4; }
    else                           { src = Wo; dst = g_woh; off = i - WQ4 - WK4 - WV4; }
    float4 v = ((const float4*)src)[off];
    ((uint2*)dst)[off] = cvt4h1(v);
}

// ---------------------------------------------------------------------------
// QKV GEMM: A fp32 (split hi/lo in-kernel), B fp16. (R14 frozen)
// CTA tile 128x64x32, 256 threads, warp tile 32x32, double-buffered.
// ---------------------------------------------------------------------------
#define BM 128
#define BN 64
#define BKK 32
#define ASTR 40
#define STAGE_ELEMS (BM*ASTR*2 + BN*ASTR)
#define SMEM_BYTES  (2 * STAGE_ELEMS * 2)

__device__ __forceinline__ void gemm_body(
    const float* __restrict__ A, const __half* __restrict__ Bg,
    float* __restrict__ Cf, __half* __restrict__ Ch,
    int N, int K, int m0, int n0, __half* sm)
{
    const int tid  = threadIdx.x;
    const int lane = tid & 31;
    const int warp = tid >> 5;
    const int wm = (warp >> 1) * 32;
    const int wn = (warp & 1) * 32;

    const int a_lr = lane & 15;
    const int a_k8 = ((lane >> 4) & 1) << 3;
    const int b_nr = (((lane >> 4) & 1) << 3) | (lane & 7);
    const int b_k8 = ((lane >> 3) & 1) << 3;

    float acc[2][4][4];
    #pragma unroll
    for (int i = 0; i < 2; i++)
        #pragma unroll
        for (int j = 0; j < 4; j++)
            #pragma unroll
            for (int t = 0; t < 4; t++) acc[i][j][t] = 0.f;

    const int b_row = tid >> 2, b_c8 = (tid & 3) << 3;
    float4 ar[4]; uint4 br;
    #pragma unroll
    for (int it = 0; it < 4; it++) {
        int f = it * 256 + tid, row = f >> 3, c4 = f & 7;
        ar[it] = *(const float4*)(A + (size_t)(m0 + row) * K + c4 * 4);
    }
    br = *(const uint4*)(Bg + (size_t)(n0 + b_row) * K + b_c8);

    for (int kb = 0; kb < K; kb += BKK) {
        const int st = (kb >> 5) & 1;
        __half* Ah = sm + st * STAGE_ELEMS;
        __half* Al = Ah + BM * ASTR;
        __half* Bh = Al + BM * ASTR;

        #pragma unroll
        for (int it = 0; it < 4; it++) {
            int f = it * 256 + tid, row = f >> 3, c4 = f & 7;
            uint2 hi, lo; cvt4h(ar[it], hi, lo);
            *(uint2*)&Ah[row * ASTR + c4 * 4] = hi;
            *(uint2*)&Al[row * ASTR + c4 * 4] = lo;
        }
        *(uint4*)&Bh[b_row * ASTR + b_c8] = br;
        __syncthreads();

        if (kb + BKK < K) {
            #pragma unroll
            for (int it = 0; it < 4; it++) {
                int f = it * 256 + tid, row = f >> 3, c4 = f & 7;
                ar[it] = *(const float4*)(A + (size_t)(m0 + row) * K + kb + BKK + c4 * 4);
            }
            br = *(const uint4*)(Bg + (size_t)(n0 + b_row) * K + kb + BKK + b_c8);
        }

        #pragma unroll
        for (int ks = 0; ks < BKK; ks += 16) {
            uint32 ah[2][4], al[2][4], bh[2][4];
            #pragma unroll
            for (int mi = 0; mi < 2; mi++) {
                int off = (wm + mi * 16 + a_lr) * ASTR + ks + a_k8;
                ldsm4(ah[mi][0], ah[mi][1], ah[mi][2], ah[mi][3], &Ah[off]);
                ldsm4(al[mi][0], al[mi][1], al[mi][2], al[mi][3], &Al[off]);
            }
            #pragma unroll
            for (int p = 0; p < 2; p++) {
                int off = (wn + p * 16 + b_nr) * ASTR + ks + b_k8;
                ldsm4(bh[p][0], bh[p][1], bh[p][2], bh[p][3], &Bh[off]);
            }
            #pragma unroll
            for (int mi = 0; mi < 2; mi++)
                #pragma unroll
                for (int ni = 0; ni < 4; ni++) {
                    int p = ni >> 1, s = (ni & 1) * 2;
                    mma16816h(acc[mi][ni], ah[mi], bh[p][s], bh[p][s+1]);
                    mma16816h(acc[mi][ni], al[mi], bh[p][s], bh[p][s+1]);
                }
        }
    }

    const int gq = lane >> 2, t = lane & 3;
    if (Ch) {
        #pragma unroll
        for (int mi = 0; mi < 2; mi++)
            #pragma unroll
            for (int ni = 0; ni < 4; ni++) {
                int row = m0 + wm + mi * 16 + gq;
                int col = n0 + wn + ni * 8 + t * 2;
                *(uint32*)(Ch + (size_t)row * N + col) =
                    pack2h(acc[mi][ni][0], acc[mi][ni][1]);
                *(uint32*)(Ch + (size_t)(row + 8) * N + col) =
                    pack2h(acc[mi][ni][2], acc[mi][ni][3]);
            }
    } else {
        #pragma unroll
        for (int mi = 0; mi < 2; mi++)
            #pragma unroll
            for (int ni = 0; ni < 4; ni++) {
                int row = m0 + wm + mi * 16 + gq;
                int col = n0 + wn + ni * 8 + t * 2;
                *(float2*)(Cf + (size_t)row * N + col)       = make_float2(acc[mi][ni][0], acc[mi][ni][1]);
                *(float2*)(Cf + (size_t)(row + 8) * N + col) = make_float2(acc[mi][ni][2], acc[mi][ni][3]);
            }
    }
}

__global__ __launch_bounds__(256, 2) void gemm_qkv(const float* __restrict__ x)
{
    extern __shared__ __half sm[];
    int nb = blockIdx.x;
    if (nb < 32)
        gemm_body(x, g_wqh, g_q, nullptr, H_*HD_, D_, blockIdx.y * BM, nb * 64, sm);
    else if (nb < 40)
        gemm_body(x, g_wkh, g_k, nullptr, G_*HD_, D_, blockIdx.y * BM, (nb - 32) * 64, sm);
    else
        gemm_body(x, g_wvh, nullptr, g_vh, G_*HD_, D_, blockIdx.y * BM, (nb - 40) * 64, sm);
}

// ---------------------------------------------------------------------------
// O-projection GEMM: BOTH operands fp16 (single term, half the MMAs).
// CTA tile 128x128x32, 256 threads, warp tile 32x64, double-buffered.
// A staging: 128 rows x 4 chunks x uint4(8h) = 512 chunks (it<2).
// B staging: 128 rows x 4 chunks x uint4(8h) = 512 chunks (it<2).
// ---------------------------------------------------------------------------
#define FSTAGE ((BM*ASTR)*2)               // Ah + Bh = 10240 halves per stage
#define FSMEM  (2 * FSTAGE * 2)            // 40960 B

__global__ __launch_bounds__(256, 2) void gemm_o(float* __restrict__ out)
{
    extern __shared__ __half sm[];
    const __half* __restrict__ Ag = g_cth;
    const __half* __restrict__ Bg = g_woh;
    const int N = D_, K = H_*HD_;
    const int m0 = blockIdx.y * BM, n0 = blockIdx.x * 128;

    const int tid  = threadIdx.x;
    const int lane = tid & 31;
    const int warp = tid >> 5;
    const int wm = (warp >> 1) * 32;   // 4 warps on M
    const int wn = (warp & 1) * 64;    // 2 warps on N

    const int a_lr = lane & 15;
    const int a_k8 = ((lane >> 4) & 1) << 3;
    const int b_nr = (((lane >> 4) & 1) << 3) | (lane & 7);
    const int b_k8 = ((lane >> 3) & 1) << 3;

    float acc[2][8][4];
    #pragma unroll
    for (int i = 0; i < 2; i++)
        #pragma unroll
        for (int j = 0; j < 8; j++)
            #pragma unroll
            for (int t = 0; t < 4; t++) acc[i][j][t] = 0.f;

    // staging: 2 uint4/thread each for A and B (512 chunks; row=f>>2, c8=(f&3)<<3)
    uint4 ar[2], br[2];
    #pragma unroll
    for (int it = 0; it < 2; it++) {
        int f = it * 256 + tid, row = f >> 2, c8 = (f & 3) << 3;
        ar[it] = *(const uint4*)(Ag + (size_t)(m0 + row) * K + c8);
        br[it] = *(const uint4*)(Bg + (size_t)(n0 + row) * K + c8);
    }

    for (int kb = 0; kb < K; kb += BKK) {
        const int st = (kb >> 5) & 1;
        __half* Ah = sm + st * FSTAGE;
        __half* Bh = Ah + BM * ASTR;

        #pragma unroll
        for (int it = 0; it < 2; it++) {
            int f = it * 256 + tid, row = f >> 2, c8 = (f & 3) << 3;
            *(uint4*)&Ah[row * ASTR + c8] = ar[it];
            *(uint4*)&Bh[row * ASTR + c8] = br[it];
        }
        __syncthreads();

        if (kb + BKK < K) {
            #pragma unroll
            for (int it = 0; it < 2; it++) {
                int f = it * 256 + tid, row = f >> 2, c8 = (f & 3) << 3;
                ar[it] = *(const uint4*)(Ag + (size_t)(m0 + row) * K + kb + BKK + c8);
                br[it] = *(const uint4*)(Bg + (size_t)(n0 + row) * K + kb + BKK + c8);
            }
        }

        #pragma unroll
        for (int ks = 0; ks < BKK; ks += 16) {
            uint32 ah[2][4], bh[4][4];
            #pragma unroll
            for (int mi = 0; mi < 2; mi++) {
                int off = (wm + mi * 16 + a_lr) * ASTR + ks + a_k8;
                ldsm4(ah[mi][0], ah[mi][1], ah[mi][2], ah[mi][3], &Ah[off]);
            }
            #pragma unroll
            for (int p = 0; p < 4; p++) {
                int off = (wn + p * 16 + b_nr) * ASTR + ks + b_k8;
                ldsm4(bh[p][0], bh[p][1], bh[p][2], bh[p][3], &Bh[off]);
            }
            #pragma unroll
            for (int mi = 0; mi < 2; mi++)
                #pragma unroll
                for (int ni = 0; ni < 8; ni++) {
                    int p = ni >> 1, s = (ni & 1) * 2;
                    mma16816h(acc[mi][ni], ah[mi], bh[p][s], bh[p][s+1]);
                }
        }
    }

    const int gq = lane >> 2, t = lane & 3;
    #pragma unroll
    for (int mi = 0; mi < 2; mi++)
        #pragma unroll
        for (int ni = 0; ni < 8; ni++) {
            int row = m0 + wm + mi * 16 + gq;
            int col = n0 + wn + ni * 8 + t * 2;
            *(float2*)(out + (size_t)row * N + col)       = make_float2(acc[mi][ni][0], acc[mi][ni][1]);
            *(float2*)(out + (size_t)(row + 8) * N + col) = make_float2(acc[mi][ni][2], acc[mi][ni][3]);
        }
}

// ---------------------------------------------------------------------------
// Fused RMSNorm + RoPE + scale, emitting fp16 (hi, optional lo). (R14 frozen)
// ---------------------------------------------------------------------------
__global__ __launch_bounds__(256) void rms_rope_h(
    const float* __restrict__ t, __half* __restrict__ th, __half* __restrict__ tl,
    const float* __restrict__ cosp, const float* __restrict__ sinp,
    const float* __restrict__ scale, int NH, float mul, int wlo)
{
    const int warp = (blockIdx.x * blockDim.x + threadIdx.x) >> 5;
    const int lane = threadIdx.x & 31;
    const int s = (warp / NH) % S_;
    const float* p = t + (size_t)warp * HD_;

    float t1 = p[lane];
    float t2 = p[lane + 32];
    float ss = t1 * t1 + t2 * t2;
    #pragma unroll
    for (int o = 16; o > 0; o >>= 1) ss += __shfl_xor_sync(0xffffffffu, ss, o);
    float rs = rsqrtf(ss * (1.0f / HD_) + 1e-6f);

    float n1 = t1 * rs * (1.0f + scale[lane]);
    float n2 = t2 * rs * (1.0f + scale[lane + 32]);

    float c1 = cosp[s * HD_ + lane],      c2 = cosp[s * HD_ + lane + 32];
    float s1 = sinp[s * HD_ + lane],      s2 = sinp[s * HD_ + lane + 32];
    float o1 = (n1 * c1 - n2 * s1) * mul;
    float o2 = (n2 * c2 + n1 * s2) * mul;

    size_t base = (size_t)warp * HD_;
    __half h1 = __float2half_rn(o1);
    __half h2 = __float2half_rn(o2);
    th[base + lane]      = h1;
    th[base + lane + 32] = h2;
    if (wlo) {
        tl[base + lane]      = __float2half_rn(o1 - __half2float(h1));
        tl[base + lane + 32] = __float2half_rn(o2 - __half2float(h2));
    }
}

// ---------------------------------------------------------------------------
// Tensor-core causal flash attention (R16 body). Epilogue now writes fp16 ctx.
// ---------------------------------------------------------------------------
#define TSTR 72
#define NEG_BIG (-1e30f)

__global__ __launch_bounds__(128, 4) void attn_tc(
    const __half* __restrict__ qh_g, const __half* __restrict__ ql_g,
    const __half* __restrict__ kh_g, const __half* __restrict__ vh_g,
    __half* __restrict__ cth)
{
    __shared__ __align__(16) __half Kh[2][64*TSTR];
    __shared__ __align__(16) __half Vh[2][64*TSTR];

    const int tid  = threadIdx.x;
    const int lane = tid & 31;
    const int warp = tid >> 5;
    const int qt = (S_/64 - 1) - blockIdx.x;   // longest-first
    const int h  = blockIdx.y, b = blockIdx.z;
    const int g  = h / GS_;
    const int q0 = qt * 64;

    const int a_lr = lane & 15;
    const int a_k8 = ((lane >> 4) & 1) << 3;
    const int b_nr = (((lane >> 4) & 1) << 3) | (lane & 7);
    const int b_k8 = ((lane >> 3) & 1) << 3;
    const int v_r  = lane & 15;

    #pragma unroll
    for (int it = 0; it < 4; it++) {
        int f = it * 128 + tid, row = f >> 3, c8 = (f & 7) << 3;
        size_t src = ((size_t)(b * S_ + q0 + row) * H_ + h) * HD_ + c8;
        *(uint4*)&Kh[1][row * TSTR + c8] = *(const uint4*)(qh_g + src);
        *(uint4*)&Vh[1][row * TSTR + c8] = *(const uint4*)(ql_g + src);
    }
    __syncthreads();

    uint32 qh[4][4], ql[4][4];
    #pragma unroll
    for (int kc = 0; kc < 4; kc++) {
        int off = (warp * 16 + a_lr) * TSTR + kc * 16 + a_k8;
        ldsm4(qh[kc][0], qh[kc][1], qh[kc][2], qh[kc][3], &Kh[1][off]);
        ldsm4(ql[kc][0], ql[kc][1], ql[kc][2], ql[kc][3], &Vh[1][off]);
    }

    float octx[8][4];
    #pragma unroll
    for (int i = 0; i < 8; i++)
        #pragma unroll
        for (int j = 0; j < 4; j++) octx[i][j] = 0.f;
    float m0 = NEG_BIG, m1 = NEG_BIG, l0 = 0.f, l1 = 0.f;

    const int ntiles = qt + 1;
    for (int t = 0; t < ntiles; t++) {
        const int kt0 = t * 64;
        const int bf  = t & 1;
        __half* Kb = Kh[bf];
        __half* Vb = Vh[bf];

        #pragma unroll
        for (int it = 0; it < 4; it++) {
            int f = it * 128 + tid, row = f >> 3, c8 = (f & 7) << 3;
            size_t src = ((size_t)(b * S_ + kt0 + row) * G_ + g) * HD_ + c8;
            *(uint4*)&Kb[row * TSTR + c8] = *(const uint4*)(kh_g + src);
            *(uint4*)&Vb[row * TSTR + c8] = *(const uint4*)(vh_g + src);
        }
        __syncthreads();

        float sc[8][4];
        #pragma unroll
        for (int i = 0; i < 8; i++)
            #pragma unroll
            for (int j = 0; j < 4; j++) sc[i][j] = 0.f;

        #pragma unroll
        for (int kg = 0; kg < 4; kg++) {
            #pragma unroll
            for (int kc = 0; kc < 4; kc++) {
                uint32 bh0, bh1, bh2, bh3;
                int off = (kg * 16 + b_nr) * TSTR + kc * 16 + b_k8;
                ldsm4(bh0, bh1, bh2, bh3, &Kb[off]);
                mma16816h(sc[2*kg],   qh[kc], bh0, bh1);
                mma16816h(sc[2*kg],   ql[kc], bh0, bh1);
                mma16816h(sc[2*kg+1], qh[kc], bh2, bh3);
                mma16816h(sc[2*kg+1], ql[kc], bh2, bh3);
            }
        }

        const int gq = lane >> 2, tt = lane & 3;
        if (kt0 == q0) {
            int qi0 = q0 + warp * 16 + gq;
            int qi1 = qi0 + 8;
            #pragma unroll
            for (int j = 0; j < 8; j++) {
                int kj = kt0 + j * 8 + tt * 2;
                if (kj     > qi0) sc[j][0] = NEG_BIG;
                if (kj + 1 > qi0) sc[j][1] = NEG_BIG;
                if (kj     > qi1) sc[j][2] = NEG_BIG;
                if (kj + 1 > qi1) sc[j][3] = NEG_BIG;
            }
        }

        float mx0 = NEG_BIG, mx1 = NEG_BIG;
        #pragma unroll
        for (int j = 0; j < 8; j++) {
            mx0 = fmaxf(mx0, fmaxf(sc[j][0], sc[j][1]));
            mx1 = fmaxf(mx1, fmaxf(sc[j][2], sc[j][3]));
        }
        #pragma unroll
        for (int o = 1; o <= 2; o <<= 1) {
            mx0 = fmaxf(mx0, __shfl_xor_sync(0xffffffffu, mx0, o));
            mx1 = fmaxf(mx1, __shfl_xor_sync(0xffffffffu, mx1, o));
        }
        mx0 = fmaxf(mx0, m0); mx1 = fmaxf(mx1, m1);
        float alpha0 = __expf(m0 - mx0), alpha1 = __expf(m1 - mx1);
        m0 = mx0; m1 = mx1;

        float s0 = 0.f, s1 = 0.f;
        #pragma unroll
        for (int j = 0; j < 8; j++) {
            sc[j][0] = __expf(sc[j][0] - m0); s0 += sc[j][0];
            sc[j][1] = __expf(sc[j][1] - m0); s0 += sc[j][1];
            sc[j][2] = __expf(sc[j][2] - m1); s1 += sc[j][2];
            sc[j][3] = __expf(sc[j][3] - m1); s1 += sc[j][3];
        }
        #pragma unroll
        for (int o = 1; o <= 2; o <<= 1) {
            s0 += __shfl_xor_sync(0xffffffffu, s0, o);
            s1 += __shfl_xor_sync(0xffffffffu, s1, o);
        }
        l0 = l0 * alpha0 + s0;
        l1 = l1 * alpha1 + s1;

        #pragma unroll
        for (int ni = 0; ni < 8; ni++) {
            octx[ni][0] *= alpha0; octx[ni][1] *= alpha0;
            octx[ni][2] *= alpha1; octx[ni][3] *= alpha1;
        }

        #pragma unroll
        for (int kc = 0; kc < 4; kc++) {
            uint32 aph[4], apl[4];
            split2h(sc[2*kc][0],   sc[2*kc][1],   aph[0], apl[0]);
            split2h(sc[2*kc][2],   sc[2*kc][3],   aph[1], apl[1]);
            split2h(sc[2*kc+1][0], sc[2*kc+1][1], aph[2], apl[2]);
            split2h(sc[2*kc+1][2], sc[2*kc+1][3], aph[3], apl[3]);
            #pragma unroll
            for (int ni = 0; ni < 8; ni++) {
                uint32 vh0, vh1;
                int off = (kc * 16 + v_r) * TSTR + ni * 8;
                ldsm2t(vh0, vh1, &Vb[off]);
                mma16816h(octx[ni], aph, vh0, vh1);
                mma16816h(octx[ni], apl, vh0, vh1);
            }
        }
    }

    // ---- Epilogue: normalize, write ctx as fp16 ----
    const int gq = lane >> 2, tt = lane & 3;
    float inv0 = 1.0f / l0, inv1 = 1.0f / l1;
    #pragma unroll
    for (int ni = 0; ni < 8; ni++) {
        int row = q0 + warp * 16 + gq;
        int col = ni * 8 + tt * 2;
        size_t d0 = ((size_t)(b * S_ + row) * H_ + h) * HD_ + col;
        size_t d1 = ((size_t)(b * S_ + row + 8) * H_ + h) * HD_ + col;
        *(uint32*)(cth + d0) = pack2h(octx[ni][0] * inv0, octx[ni][1] * inv0);
        *(uint32*)(cth + d1) = pack2h(octx[ni][2] * inv1, octx[ni][3] * inv1);
    }
}

// ---------------------------------------------------------------------------
// Launch
// ---------------------------------------------------------------------------
extern "C" void kernel_launch(void* const* d_in, const int* in_sizes, int n_in,
                              void* d_out, int out_size)
{
    (void)in_sizes; (void)n_in; (void)out_size;
    const float* x    = (const float*)d_in[0];
    const float* cosp = (const float*)d_in[2];
    const float* sinp = (const float*)d_in[3];
    const float* Wq   = (const float*)d_in[4];
    const float* Wk   = (const float*)d_in[5];
    const float* Wv   = (const float*)d_in[6];
    const float* Wo   = (const float*)d_in[7];
    const float* qsc  = (const float*)d_in[8];
    const float* ksc  = (const float*)d_in[9];
    float* out = (float*)d_out;

    float *pq, *pk;
    __half *pqh, *pql, *pkh, *pvh, *pcth;
    cudaGetSymbolAddress((void**)&pq, g_q);
    cudaGetSymbolAddress((void**)&pk, g_k);
    cudaGetSymbolAddress((void**)&pqh, g_qh);
    cudaGetSymbolAddress((void**)&pql, g_ql);
    cudaGetSymbolAddress((void**)&pkh, g_kh);
    cudaGetSymbolAddress((void**)&pvh, g_vh);
    cudaGetSymbolAddress((void**)&pcth, g_cth);

    static bool attr_done = false;
    if (!attr_done) {
        cudaFuncSetAttribute(gemm_qkv, cudaFuncAttributeMaxDynamicSharedMemorySize, SMEM_BYTES);
        cudaFuncSetAttribute(gemm_o,   cudaFuncAttributeMaxDynamicSharedMemorySize, FSMEM);
        attr_done = true;
    }

    // weights -> fp16 (once per launch)
    wconv<<<(WTOT4 + 255) / 256, 256>>>(Wq, Wk, Wv, Wo);

    // merged QKV projection (v written fp16 directly)
    gemm_qkv<<<dim3(48, M_/BM), 256, SMEM_BYTES>>>(x);

    // rmsnorm + rope -> fp16 (q: hi+lo, k: hi only)
    rms_rope_h<<<(M_*H_)/8, 256>>>(pq, pqh, pql, cosp, sinp, qsc, H_, 0.125f, 1);
    rms_rope_h<<<(M_*G_)/8, 256>>>(pk, pkh, nullptr, cosp, sinp, ksc, G_, 1.0f, 0);

    // attention (fp16 in/out, longest-first)
    attn_tc<<<dim3(S_/64, H_, B_), 128>>>(pqh, pql, pkh, pvh, pcth);

    // output projection (pure fp16 operands, single term)
    gemm_o<<<dim3(D_/128, M_/BM), 256, FSMEM>>>(out);
}